// round 10
// baseline (speedup 1.0000x reference)
#include <cuda_runtime.h>
#include <cfloat>
#include <math.h>

// Problem shape (fixed by the reference)
#define B_    32
#define N_    4096
#define D_    256
#define K_    1024
#define NROWS (B_ * N_)          // 131072 rows of z_e

#define MARGIN_ 0.02f            // flag threshold for tie-aware exact recheck

// Scratch (static device globals -- no allocation allowed)
__device__ float  g_esq[K_];     // fp32 e_sq for the fast path
__device__ double g_esqd[K_];    // exact e_sq for the fixup
__device__ int    g_idx[NROWS];
__device__ int    g_nflag;
__device__ int    g_flags[NROWS];

// ---------------------------------------------------------------------------
// Kernel 1: per-code squared norms, fp32 (fast path) + fp64 (exact, fixup).
// One warp per code; also resets the flag counter.
// 128 blocks x 256 threads (8 warps/block, 1 code/warp).
// ---------------------------------------------------------------------------
__global__ void esq_kernel(const float* __restrict__ cb) {
    if (blockIdx.x == 0 && threadIdx.x == 0) g_nflag = 0;
    const int k    = blockIdx.x * 8 + (threadIdx.x >> 5);
    const int lane = threadIdx.x & 31;
    const float* row = cb + (size_t)k * D_;
    double sd = 0.0;
    #pragma unroll
    for (int j = 0; j < 8; j++) {
        const double x = (double)row[lane + 32 * j];
        sd = fma(x, x, sd);
    }
    #pragma unroll
    for (int off = 16; off > 0; off >>= 1)
        sd += __shfl_down_sync(0xffffffffu, sd, off);
    if (lane == 0) {
        g_esqd[k] = sd;
        g_esq[k]  = (float)sd;
    }
}

// ---------------------------------------------------------------------------
// Kernel 2: fused GEMM + argmin (+ second-best margin tracking).
// Block tile: 128 rows x 128 codes, 8x8 register tile per thread (256 thr).
// dist candidate = e_sq[k] - 2*dot (z_sq is row-constant, argmin-invariant).
// Rows whose best/second-best gap < MARGIN_ go to the tie-aware fixup.
// ---------------------------------------------------------------------------
__global__ __launch_bounds__(256) void vq_argmin_kernel(
    const float* __restrict__ z, const float* __restrict__ cb,
    float* __restrict__ idx_out)
{
    __shared__ __align__(16) float zs[8][128];
    __shared__ __align__(16) float es[8][128];
    __shared__ float redv[128][17];
    __shared__ int   redi[128][17];
    __shared__ float reds[128][17];

    const int tid = threadIdx.x;
    const int tx  = tid & 15;    // code-dim thread coord
    const int ty  = tid >> 4;    // row-dim thread coord
    const int rowBase = blockIdx.x * 128;

    const int lr = tid & 127;         // load row / code within tile
    const int dh = (tid >> 7) * 4;    // which half of the 8-wide d chunk

    float bestv[8], secondv[8];
    int   besti[8];
    #pragma unroll
    for (int i = 0; i < 8; i++) {
        bestv[i] = FLT_MAX; secondv[i] = FLT_MAX; besti[i] = 0;
    }

    for (int kt = 0; kt < 8; kt++) {           // 8 code tiles of 128
        const int kBase = kt * 128;
        float acc[8][8];
        #pragma unroll
        for (int i = 0; i < 8; i++)
            #pragma unroll
            for (int j = 0; j < 8; j++) acc[i][j] = 0.f;

        for (int dk = 0; dk < D_; dk += 8) {   // 32 d-chunks
            const float4 zv = *(const float4*)(z  + (size_t)(rowBase + lr) * D_ + dk + dh);
            const float4 ev = *(const float4*)(cb + (size_t)(kBase   + lr) * D_ + dk + dh);
            __syncthreads();   // previous chunk's compute done before overwrite
            zs[dh + 0][lr] = zv.x; zs[dh + 1][lr] = zv.y;
            zs[dh + 2][lr] = zv.z; zs[dh + 3][lr] = zv.w;
            es[dh + 0][lr] = ev.x; es[dh + 1][lr] = ev.y;
            es[dh + 2][lr] = ev.z; es[dh + 3][lr] = ev.w;
            __syncthreads();

            #pragma unroll
            for (int d = 0; d < 8; d++) {
                const float4 a0 = *(const float4*)&zs[d][ty * 4];
                const float4 a1 = *(const float4*)&zs[d][ty * 4 + 64];
                const float4 b0 = *(const float4*)&es[d][tx * 4];
                const float4 b1 = *(const float4*)&es[d][tx * 4 + 64];
                const float a[8]  = {a0.x, a0.y, a0.z, a0.w, a1.x, a1.y, a1.z, a1.w};
                const float bb[8] = {b0.x, b0.y, b0.z, b0.w, b1.x, b1.y, b1.z, b1.w};
                #pragma unroll
                for (int i = 0; i < 8; i++)
                    #pragma unroll
                    for (int j = 0; j < 8; j++)
                        acc[i][j] = fmaf(a[i], bb[j], acc[i][j]);
            }
        }

        // Fused argmin epilogue for this code tile (registers only)
        #pragma unroll
        for (int j = 0; j < 8; j++) {
            const int c = kBase + ((j < 4) ? tx * 4 + j : 64 + tx * 4 + (j - 4));
            const float eq = g_esq[c];
            #pragma unroll
            for (int i = 0; i < 8; i++) {
                const float cand = fmaf(-2.f, acc[i][j], eq);
                if (cand < bestv[i] || (cand == bestv[i] && c < besti[i])) {
                    secondv[i] = bestv[i];
                    bestv[i] = cand; besti[i] = c;
                } else {
                    secondv[i] = fminf(secondv[i], cand);
                }
            }
        }
    }

    // Cross-thread argmin (+ second-best) merge: 16 tx-threads share each row
    __syncthreads();
    #pragma unroll
    for (int i = 0; i < 8; i++) {
        const int row = (i < 4) ? ty * 4 + i : 64 + ty * 4 + (i - 4);
        redv[row][tx] = bestv[i];
        redi[row][tx] = besti[i];
        reds[row][tx] = secondv[i];
    }
    __syncthreads();
    if (tid < 128) {
        float bv = redv[tid][0];
        int   bi = redi[tid][0];
        float bs = reds[tid][0];
        #pragma unroll
        for (int t = 1; t < 16; t++) {
            const float v  = redv[tid][t];
            const int   ix = redi[tid][t];
            const float s2 = reds[tid][t];
            if (v < bv || (v == bv && ix < bi)) {
                bs = fminf(fminf(bv, bs), s2);
                bv = v; bi = ix;
            } else {
                bs = fminf(bs, fminf(v, s2));
            }
        }
        g_idx[rowBase + tid] = bi;
        if (idx_out) idx_out[rowBase + tid] = (float)bi;
        if (bs - bv < MARGIN_) {                       // near-tie: tie-aware recheck
            const int p = atomicAdd(&g_nflag, 1);
            g_flags[p] = rowBase + tid;
        }
    }
}

// ---------------------------------------------------------------------------
// Kernel 3: tie-aware EXACT refinement of flagged near-tie rows.
// Computes full distances exactly in fp64:
//     dist[c] = z_sq + e_sq[c] - 2*dot(z,e_c)
// then models the reference's fp32 quantization: distances within
//     T = ulp_f32(best_dist) + 4e-5
// of the exact minimum are treated as an fp32 TIE, resolved (like jnp.argmin)
// by LOWEST INDEX. Rationale (R3/R4/R5/R8 bit evidence): the reference's
// dists live on a ~3-6e-5 fp32 grid; sub-ulp pairs collapse to exact ties in
// the reference, where argmin picks the first occurrence -- the exact argmin
// provably mismatches it (R4), and order-emulation guesses are uncorrelated
// coin flips (R5/R8). For gaps > ~2 ulp this rule IS the exact argmin.
// One block per flagged row, grid-stride; fp64 volume ~190 rows -> ~15 us.
// ---------------------------------------------------------------------------
__global__ __launch_bounds__(256) void fixup_kernel(
    const float* __restrict__ z, const float* __restrict__ cb,
    float* __restrict__ idx_out)
{
    __shared__ __align__(16) float zrow[D_];
    __shared__ double dred[256];
    __shared__ int    si[256];
    const int tid = threadIdx.x;
    const int n = g_nflag;

    for (int f = blockIdx.x; f < n; f += gridDim.x) {
        const int row = g_flags[f];
        __syncthreads();                       // protect smem reuse across iters
        zrow[tid] = z[(size_t)row * D_ + tid];
        __syncthreads();

        // z_sq exactly (fp64 block tree-reduce)
        {
            const double x = (double)zrow[tid];
            dred[tid] = x * x;
        }
        __syncthreads();
        #pragma unroll
        for (int off = 128; off > 0; off >>= 1) {
            if (tid < off) dred[tid] += dred[tid + off];
            __syncthreads();
        }
        const double zsqd = dred[0];
        __syncthreads();

        // Each thread scores 4 codes: tid, tid+256, tid+512, tid+768 (fp64)
        double dists[4];
        double bestd = 1e300;
        #pragma unroll
        for (int j = 0; j < 4; j++) {
            const int c = j * 256 + tid;
            const float4* e4 = (const float4*)(cb + (size_t)c * D_);
            double dot = 0.0;
            #pragma unroll 8
            for (int q = 0; q < D_ / 4; q++) {
                const float4 ev = e4[q];
                const float4 zv = *(const float4*)&zrow[q * 4];
                dot = fma((double)zv.x, (double)ev.x, dot);
                dot = fma((double)zv.y, (double)ev.y, dot);
                dot = fma((double)zv.z, (double)ev.z, dot);
                dot = fma((double)zv.w, (double)ev.w, dot);
            }
            const double dd = zsqd + (g_esqd[c] - 2.0 * dot);
            dists[j] = dd;
            if (dd < bestd) bestd = dd;
        }

        // Block-reduce the exact minimum value
        dred[tid] = bestd;
        __syncthreads();
        #pragma unroll
        for (int off = 128; off > 0; off >>= 1) {
            if (tid < off) dred[tid] = fmin(dred[tid], dred[tid + off]);
            __syncthreads();
        }
        const double bestFull = dred[0];
        __syncthreads();

        // fp32-tie window: ulp of best at fp32 precision, + reference noise slack
        double T;
        if (bestFull > 1.0) T = ldexp(1.0, ilogb(bestFull) - 23) + 4e-5;
        else                T = 5e-5;
        const double lim = bestFull + T;

        // Lowest index within the tie window
        int mi = 0x7fffffff;
        #pragma unroll
        for (int j = 0; j < 4; j++)
            if (dists[j] <= lim) mi = min(mi, j * 256 + tid);
        si[tid] = mi;
        __syncthreads();
        #pragma unroll
        for (int off = 128; off > 0; off >>= 1) {
            if (tid < off) si[tid] = min(si[tid], si[tid + off]);
            __syncthreads();
        }
        if (tid == 0) {
            g_idx[row] = si[0];
            if (idx_out) idx_out[row] = (float)si[0];
        }
    }
}

// ---------------------------------------------------------------------------
// Kernel 4: gather codebook rows into z_q_st and z_q.
// z_q    = codebook[idx]                          (raw gather)
// z_q_st = fl( z_e + fl(z_q - z_e) )              (reference STE rounding)
// 4 rows per 256-thread block; float4 traffic; codebook stays L2-resident.
// ---------------------------------------------------------------------------
__global__ void gather_kernel(const float* __restrict__ cb,
                              const float* __restrict__ z,
                              float* __restrict__ out_st,
                              float* __restrict__ out_q)
{
    const int r    = blockIdx.x * 4 + (threadIdx.x >> 6);
    const int lane = threadIdx.x & 63;
    const int idx  = g_idx[r];
    const float4 v = *(const float4*)(cb + (size_t)idx * D_ + lane * 4);
    if (out_q) *(float4*)(out_q + (size_t)r * D_ + lane * 4) = v;
    if (out_st) {
        const float4 zv = *(const float4*)(z + (size_t)r * D_ + lane * 4);
        float4 st;
        st.x = __fadd_rn(zv.x, __fsub_rn(v.x, zv.x));
        st.y = __fadd_rn(zv.y, __fsub_rn(v.y, zv.y));
        st.z = __fadd_rn(zv.z, __fsub_rn(v.z, zv.z));
        st.w = __fadd_rn(zv.w, __fsub_rn(v.w, zv.w));
        *(float4*)(out_st + (size_t)r * D_ + lane * 4) = st;
    }
}

// ---------------------------------------------------------------------------
extern "C" void kernel_launch(void* const* d_in, const int* in_sizes, int n_in,
                              void* d_out, int out_size) {
    const float* z  = (const float*)d_in[0];   // z_e      [32,4096,256] f32
    const float* cb = (const float*)d_in[1];   // codebook [1024,256]    f32
    float* out = (float*)d_out;

    const long long bnd = (long long)NROWS * D_;   // 33,554,432
    float *p_st = nullptr, *p_q = nullptr, *p_idx = nullptr;
    const long long os = (long long)out_size;

    if (os >= 2 * bnd + NROWS) {                 // [z_q_st | z_q | indices]
        p_st = out; p_q = out + bnd; p_idx = out + 2 * bnd;
    } else if (os == 2 * bnd) {                  // [z_q_st | z_q]
        p_st = out; p_q = out + bnd;
    } else if (os == bnd + NROWS) {              // [z_q_st | indices]
        p_st = out; p_idx = out + bnd;
    } else if (os == bnd) {                      // [z_q_st]
        p_st = out;
    } else if (os == NROWS) {                    // [indices]
        p_idx = out;
    } else {                                     // fallback
        p_st = out;
    }

    esq_kernel<<<K_ / 8, 256>>>(cb);
    vq_argmin_kernel<<<NROWS / 128, 256>>>(z, cb, p_idx);
    fixup_kernel<<<512, 256>>>(z, cb, p_idx);
    if (p_st || p_q)
        gather_kernel<<<NROWS / 4, 256>>>(cb, z, p_st, p_q);
}

// round 12
// speedup vs baseline: 1.8630x; 1.8630x over previous
#include <cuda_runtime.h>
#include <cuda_bf16.h>
#include <cfloat>
#include <math.h>
#include <cstdint>

// Problem shape (fixed by the reference)
#define B_    32
#define N_    4096
#define D_    256
#define K_    1024
#define NROWS (B_ * N_)          // 131072 rows of z_e

#define MARGIN_ 0.02f            // flag threshold for tie-aware exact recheck

// Scratch (static device globals -- no allocation allowed)
__device__ float  g_esq[K_];     // fp32 e_sq for the fast path
__device__ double g_esqd[K_];    // exact e_sq for the fixup
__device__ int    g_idx[NROWS];
__device__ int    g_nflag;
__device__ int    g_flags[NROWS];

// ---------------------------------------------------------------------------
// SMEM layout for the MMA kernel (dynamic). Padded strides: row-to-row bank
// offset = 16B -> conflict-free ldmatrix (8 rows span 128B of banks).
// ---------------------------------------------------------------------------
#define A_STRIDE 264                       // 256 + 8 bf16
#define B_STRIDE 72                        // 64 + 8 bf16
#define SM_ESQ   0                         // 1024 f32 = 4 KB
#define SM_AH    4096                      // 128*264*2 = 67584
#define SM_AL    (SM_AH + 67584)
#define SM_BH    (SM_AL + 67584)           // 128*72*2 = 18432
#define SM_BL    (SM_BH + 18432)
#define SM_RED   (SM_BL + 18432)           // 128*4*(4+4+4) = 6144
#define SM_TOTAL (SM_RED + 6144)           // 182272 B

__device__ __forceinline__ uint32_t smem_u32(const void* p) {
    uint32_t a;
    asm("{ .reg .u64 t; cvta.to.shared.u64 t, %1; cvt.u32.u64 %0, t; }"
        : "=r"(a) : "l"(p));
    return a;
}

__device__ __forceinline__ void ldmx4(uint32_t* r, uint32_t addr) {
    asm volatile("ldmatrix.sync.aligned.m8n8.x4.shared.b16 {%0,%1,%2,%3}, [%4];"
                 : "=r"(r[0]), "=r"(r[1]), "=r"(r[2]), "=r"(r[3]) : "r"(addr));
}

__device__ __forceinline__ void mma_bf16(float* c, const uint32_t* a,
                                         uint32_t b0, uint32_t b1) {
    asm volatile(
        "mma.sync.aligned.m16n8k16.row.col.f32.bf16.bf16.f32 "
        "{%0,%1,%2,%3}, {%4,%5,%6,%7}, {%8,%9}, {%0,%1,%2,%3};"
        : "+f"(c[0]), "+f"(c[1]), "+f"(c[2]), "+f"(c[3])
        : "r"(a[0]), "r"(a[1]), "r"(a[2]), "r"(a[3]), "r"(b0), "r"(b1));
}

__device__ __forceinline__ uint32_t pack_bf16x2(float x, float y) {
    const __nv_bfloat162 h = __floats2bfloat162_rn(x, y);
    return *(const uint32_t*)&h;
}

// ---------------------------------------------------------------------------
// Kernel 1: per-code squared norms, fp32 (fast path) + fp64 (exact, fixup).
// ---------------------------------------------------------------------------
__global__ void esq_kernel(const float* __restrict__ cb) {
    if (blockIdx.x == 0 && threadIdx.x == 0) g_nflag = 0;
    const int k    = blockIdx.x * 8 + (threadIdx.x >> 5);
    const int lane = threadIdx.x & 31;
    const float* row = cb + (size_t)k * D_;
    double sd = 0.0;
    #pragma unroll
    for (int j = 0; j < 8; j++) {
        const double x = (double)row[lane + 32 * j];
        sd = fma(x, x, sd);
    }
    #pragma unroll
    for (int off = 16; off > 0; off >>= 1)
        sd += __shfl_down_sync(0xffffffffu, sd, off);
    if (lane == 0) {
        g_esqd[k] = sd;
        g_esq[k]  = (float)sd;
    }
}

// ---------------------------------------------------------------------------
// Kernel 2: bf16-split warp-MMA GEMM + fused argmin.
// Baseline-PTX tensor path (mma.sync m16n8k16 bf16 + ldmatrix) -- works on
// compute_103 (non-'a'); tcgen05 does NOT (R11 ptxas evidence).
// Grid 1024 CTAs x 256 threads (8 warps, 2m x 4n, each warp 64x32).
// A = z rows (hi+lo bf16) resident in padded smem; B = codebook streamed per
// 128-code tile in 64-dim chunks. dot ~= zh*eh + zh*el + zl*eh in fp32 accum
// (error ~1e-4 << MARGIN). mma.sync is register-synchronous, so plain
// __syncthreads() guards the B buffer. Argmin folded from D fragments.
// ---------------------------------------------------------------------------
__global__ __launch_bounds__(256, 1) void vq_argmin_mma(
    const float* __restrict__ z, const float* __restrict__ cb,
    float* __restrict__ idx_out)
{
    extern __shared__ __align__(16) char smem[];
    const uint32_t sbase = smem_u32(smem);
    const int tid  = threadIdx.x;
    const int wid  = tid >> 5;
    const int lane = tid & 31;
    const int rowBase = blockIdx.x * 128;

    const int warp_m = wid & 1;          // 0..1 (64 rows each)
    const int warp_n = wid >> 1;         // 0..3 (32 cols each)
    const int g = lane >> 2;             // row group within fragment
    const int q = lane & 3;              // col pair within fragment

    // esq -> smem
    #pragma unroll
    for (int i = 0; i < 4; i++)
        *(float*)(smem + SM_ESQ + (tid + i * 256) * 4) = g_esq[tid + i * 256];

    // A: convert 128x256 fp32 -> bf16 hi/lo into padded smem.
    // 8192 float4 total, 32 per thread: idx = it*256+tid, row = idx>>6, c4 = idx&63.
    #pragma unroll 4
    for (int it = 0; it < 32; it++) {
        const int idx = it * 256 + tid;
        const int row = idx >> 6;
        const int c4  = idx & 63;
        const float4 v = *(const float4*)(z + (size_t)(rowBase + row) * D_ + c4 * 4);
        uint2 hh, ll;
        hh.x = pack_bf16x2(v.x, v.y);
        hh.y = pack_bf16x2(v.z, v.w);
        const __nv_bfloat162* hp0 = (const __nv_bfloat162*)&hh.x;
        const __nv_bfloat162* hp1 = (const __nv_bfloat162*)&hh.y;
        ll.x = pack_bf16x2(__fsub_rn(v.x, __bfloat162float(hp0->x)),
                           __fsub_rn(v.y, __bfloat162float(hp0->y)));
        ll.y = pack_bf16x2(__fsub_rn(v.z, __bfloat162float(hp1->x)),
                           __fsub_rn(v.w, __bfloat162float(hp1->y)));
        const uint32_t off = (uint32_t)row * (A_STRIDE * 2) + c4 * 8;
        *(uint2*)(smem + SM_AH + off) = hh;
        *(uint2*)(smem + SM_AL + off) = ll;
    }

    // ldmatrix per-lane base addresses.
    // A (x4): m0 rows0-7/k0-7, m1 rows8-15/k0-7, m2 rows0-7/k8-15, m3 rows8-15/k8-15
    const int a_row_off = (lane & 7) + ((lane >> 3) & 1) * 8;
    const int a_k_off   = (lane >> 4) * 8;
    uint32_t aBaseH[4], aBaseL[4];
    #pragma unroll
    for (int mi = 0; mi < 4; mi++) {
        const uint32_t e = (uint32_t)(warp_m * 64 + mi * 16 + a_row_off) * A_STRIDE
                         + a_k_off;
        aBaseH[mi] = sbase + SM_AH + e * 2;
        aBaseL[mi] = sbase + SM_AL + e * 2;
    }
    // B (x4): m0 n0-7/k0-7, m1 n0-7/k8-15, m2 n8-15/k0-7, m3 n8-15/k8-15
    const int b_n_off = (lane & 7) + (lane >> 4) * 8;
    const int b_k_off = ((lane >> 3) & 1) * 8;
    uint32_t bBaseH[2], bBaseL[2];
    #pragma unroll
    for (int nj = 0; nj < 2; nj++) {
        const uint32_t e = (uint32_t)(warp_n * 32 + nj * 16 + b_n_off) * B_STRIDE
                         + b_k_off;
        bBaseH[nj] = sbase + SM_BH + e * 2;
        bBaseL[nj] = sbase + SM_BL + e * 2;
    }

    // Per-thread argmin state: rows (warp_m*64 + mi*16 + h*8 + g), mi=0..3, h=0..1
    float bestv[4][2], secondv[4][2];
    int   besti[4][2];
    #pragma unroll
    for (int mi = 0; mi < 4; mi++)
        #pragma unroll
        for (int h = 0; h < 2; h++) {
            bestv[mi][h] = FLT_MAX; secondv[mi][h] = FLT_MAX; besti[mi][h] = 0;
        }

    for (int kt = 0; kt < 8; kt++) {
        float acc[4][4][4];
        #pragma unroll
        for (int mi = 0; mi < 4; mi++)
            #pragma unroll
            for (int n8 = 0; n8 < 4; n8++)
                #pragma unroll
                for (int u = 0; u < 4; u++) acc[mi][n8][u] = 0.f;

        for (int dk = 0; dk < 4; dk++) {
            __syncthreads();   // all warps done with previous B chunk (mma.sync is sync)
            // load + convert B chunk: 128 codes x 64 dims. 2048 float4, 8/thread.
            #pragma unroll
            for (int it = 0; it < 8; it++) {
                const int idx  = it * 256 + tid;
                const int code = idx >> 4;
                const int c4   = idx & 15;
                const float4 v = *(const float4*)(cb +
                    (size_t)(kt * 128 + code) * D_ + dk * 64 + c4 * 4);
                uint2 hh, ll;
                hh.x = pack_bf16x2(v.x, v.y);
                hh.y = pack_bf16x2(v.z, v.w);
                const __nv_bfloat162* hp0 = (const __nv_bfloat162*)&hh.x;
                const __nv_bfloat162* hp1 = (const __nv_bfloat162*)&hh.y;
                ll.x = pack_bf16x2(__fsub_rn(v.x, __bfloat162float(hp0->x)),
                                   __fsub_rn(v.y, __bfloat162float(hp0->y)));
                ll.y = pack_bf16x2(__fsub_rn(v.z, __bfloat162float(hp1->x)),
                                   __fsub_rn(v.w, __bfloat162float(hp1->y)));
                const uint32_t off = (uint32_t)code * (B_STRIDE * 2) + c4 * 8;
                *(uint2*)(smem + SM_BH + off) = hh;
                *(uint2*)(smem + SM_BL + off) = ll;
            }
            __syncthreads();

            #pragma unroll
            for (int ks = 0; ks < 4; ks++) {
                const uint32_t akOff = (uint32_t)(dk * 64 + ks * 16) * 2;
                const uint32_t bkOff = (uint32_t)(ks * 16) * 2;
                uint32_t ah[4][4], al[4][4], bh[2][4], bl[2][4];
                #pragma unroll
                for (int mi = 0; mi < 4; mi++) {
                    ldmx4(ah[mi], aBaseH[mi] + akOff);
                    ldmx4(al[mi], aBaseL[mi] + akOff);
                }
                #pragma unroll
                for (int nj = 0; nj < 2; nj++) {
                    ldmx4(bh[nj], bBaseH[nj] + bkOff);
                    ldmx4(bl[nj], bBaseL[nj] + bkOff);
                }
                #pragma unroll
                for (int mi = 0; mi < 4; mi++)
                    #pragma unroll
                    for (int n8 = 0; n8 < 4; n8++) {
                        const int nj = n8 >> 1, s = (n8 & 1) * 2;
                        mma_bf16(acc[mi][n8], ah[mi], bh[nj][s], bh[nj][s + 1]);
                        mma_bf16(acc[mi][n8], ah[mi], bl[nj][s], bl[nj][s + 1]);
                        mma_bf16(acc[mi][n8], al[mi], bh[nj][s], bh[nj][s + 1]);
                    }
            }
        }

        // Fold this code tile into running argmin.
        // D frag: c0:(g, 2q) c1:(g, 2q+1) c2:(g+8, 2q) c3:(g+8, 2q+1)
        #pragma unroll
        for (int mi = 0; mi < 4; mi++)
            #pragma unroll
            for (int n8 = 0; n8 < 4; n8++) {
                const int cbase = kt * 128 + warp_n * 32 + n8 * 8 + q * 2;
                const float e0 = *(const float*)(smem + SM_ESQ + (cbase + 0) * 4);
                const float e1 = *(const float*)(smem + SM_ESQ + (cbase + 1) * 4);
                #pragma unroll
                for (int h = 0; h < 2; h++) {
                    const float d0 = fmaf(-2.f, acc[mi][n8][h * 2 + 0], e0);
                    const float d1 = fmaf(-2.f, acc[mi][n8][h * 2 + 1], e1);
                    float* bv = &bestv[mi][h]; float* sv = &secondv[mi][h];
                    int*   bi = &besti[mi][h];
                    if (d0 < *bv) { *sv = *bv; *bv = d0; *bi = cbase; }
                    else            *sv = fminf(*sv, d0);
                    if (d1 < *bv) { *sv = *bv; *bv = d1; *bi = cbase + 1; }
                    else            *sv = fminf(*sv, d1);
                }
            }
    }

    // Quad merge (lanes 4g+0..3 hold the same rows, different cols)
    #pragma unroll
    for (int mi = 0; mi < 4; mi++)
        #pragma unroll
        for (int h = 0; h < 2; h++) {
            float bv = bestv[mi][h], s2 = secondv[mi][h];
            int   bi = besti[mi][h];
            #pragma unroll
            for (int off = 1; off <= 2; off <<= 1) {
                const float ob = __shfl_xor_sync(0xffffffffu, bv, off);
                const float os = __shfl_xor_sync(0xffffffffu, s2, off);
                const int   oi = __shfl_xor_sync(0xffffffffu, bi, off);
                const float bmax = fmaxf(bv, ob);
                const float smin = fminf(s2, os);
                if (ob < bv || (ob == bv && oi < bi)) { bv = ob; bi = oi; }
                s2 = fminf(smin, bmax);
            }
            bestv[mi][h] = bv; secondv[mi][h] = s2; besti[mi][h] = bi;
        }

    // Cross-n-warp merge through smem
    float* redb = (float*)(smem + SM_RED);            // [128][4]
    float* reds = (float*)(smem + SM_RED + 2048);     // [128][4]
    int*   redi = (int*)  (smem + SM_RED + 4096);     // [128][4]
    __syncthreads();
    if (q == 0) {
        #pragma unroll
        for (int mi = 0; mi < 4; mi++)
            #pragma unroll
            for (int h = 0; h < 2; h++) {
                const int r = warp_m * 64 + mi * 16 + h * 8 + g;
                redb[r * 4 + warp_n] = bestv[mi][h];
                reds[r * 4 + warp_n] = secondv[mi][h];
                redi[r * 4 + warp_n] = besti[mi][h];
            }
    }
    __syncthreads();
    if (tid < 128) {
        float bv = redb[tid * 4], s2 = reds[tid * 4];
        int   bi = redi[tid * 4];
        #pragma unroll
        for (int t = 1; t < 4; t++) {
            const float ob = redb[tid * 4 + t];
            const float os = reds[tid * 4 + t];
            const int   oi = redi[tid * 4 + t];
            const float bmax = fmaxf(bv, ob);
            const float smin = fminf(s2, os);
            if (ob < bv || (ob == bv && oi < bi)) { bv = ob; bi = oi; }
            s2 = fminf(smin, bmax);
        }
        const int row = rowBase + tid;
        g_idx[row] = bi;
        if (idx_out) idx_out[row] = (float)bi;
        if (s2 - bv < MARGIN_) {
            const int p = atomicAdd(&g_nflag, 1);
            g_flags[p] = row;
        }
    }
}

// ---------------------------------------------------------------------------
// Kernel 3: tie-aware EXACT refinement of flagged near-tie rows (unchanged,
// validated in R10: exact fp64 distances; distances within
// ulp_f32(best)+4e-5 of the exact min are an fp32 TIE -> lowest index).
// ---------------------------------------------------------------------------
__global__ __launch_bounds__(256) void fixup_kernel(
    const float* __restrict__ z, const float* __restrict__ cb,
    float* __restrict__ idx_out)
{
    __shared__ __align__(16) float zrow[D_];
    __shared__ double dred[256];
    __shared__ int    si[256];
    const int tid = threadIdx.x;
    const int n = g_nflag;

    for (int f = blockIdx.x; f < n; f += gridDim.x) {
        const int row = g_flags[f];
        __syncthreads();
        zrow[tid] = z[(size_t)row * D_ + tid];
        __syncthreads();

        {
            const double x = (double)zrow[tid];
            dred[tid] = x * x;
        }
        __syncthreads();
        #pragma unroll
        for (int off = 128; off > 0; off >>= 1) {
            if (tid < off) dred[tid] += dred[tid + off];
            __syncthreads();
        }
        const double zsqd = dred[0];
        __syncthreads();

        double dists[4];
        double bestd = 1e300;
        #pragma unroll
        for (int j = 0; j < 4; j++) {
            const int c = j * 256 + tid;
            const float4* e4 = (const float4*)(cb + (size_t)c * D_);
            double dot = 0.0;
            #pragma unroll 8
            for (int qd = 0; qd < D_ / 4; qd++) {
                const float4 ev = e4[qd];
                const float4 zv = *(const float4*)&zrow[qd * 4];
                dot = fma((double)zv.x, (double)ev.x, dot);
                dot = fma((double)zv.y, (double)ev.y, dot);
                dot = fma((double)zv.z, (double)ev.z, dot);
                dot = fma((double)zv.w, (double)ev.w, dot);
            }
            const double dd = zsqd + (g_esqd[c] - 2.0 * dot);
            dists[j] = dd;
            if (dd < bestd) bestd = dd;
        }

        dred[tid] = bestd;
        __syncthreads();
        #pragma unroll
        for (int off = 128; off > 0; off >>= 1) {
            if (tid < off) dred[tid] = fmin(dred[tid], dred[tid + off]);
            __syncthreads();
        }
        const double bestFull = dred[0];
        __syncthreads();

        double T;
        if (bestFull > 1.0) T = ldexp(1.0, ilogb(bestFull) - 23) + 4e-5;
        else                T = 5e-5;
        const double lim = bestFull + T;

        int mi = 0x7fffffff;
        #pragma unroll
        for (int j = 0; j < 4; j++)
            if (dists[j] <= lim) mi = min(mi, j * 256 + tid);
        si[tid] = mi;
        __syncthreads();
        #pragma unroll
        for (int off = 128; off > 0; off >>= 1) {
            if (tid < off) si[tid] = min(si[tid], si[tid + off]);
            __syncthreads();
        }
        if (tid == 0) {
            g_idx[row] = si[0];
            if (idx_out) idx_out[row] = (float)si[0];
        }
    }
}

// ---------------------------------------------------------------------------
// Kernel 4: gather codebook rows into z_q_st and z_q (DRAM-bound, ~68% peak).
// ---------------------------------------------------------------------------
__global__ void gather_kernel(const float* __restrict__ cb,
                              const float* __restrict__ z,
                              float* __restrict__ out_st,
                              float* __restrict__ out_q)
{
    const int r    = blockIdx.x * 4 + (threadIdx.x >> 6);
    const int lane = threadIdx.x & 63;
    const int idx  = g_idx[r];
    const float4 v = *(const float4*)(cb + (size_t)idx * D_ + lane * 4);
    if (out_q) *(float4*)(out_q + (size_t)r * D_ + lane * 4) = v;
    if (out_st) {
        const float4 zv = *(const float4*)(z + (size_t)r * D_ + lane * 4);
        float4 st;
        st.x = __fadd_rn(zv.x, __fsub_rn(v.x, zv.x));
        st.y = __fadd_rn(zv.y, __fsub_rn(v.y, zv.y));
        st.z = __fadd_rn(zv.z, __fsub_rn(v.z, zv.z));
        st.w = __fadd_rn(zv.w, __fsub_rn(v.w, zv.w));
        *(float4*)(out_st + (size_t)r * D_ + lane * 4) = st;
    }
}

// ---------------------------------------------------------------------------
extern "C" void kernel_launch(void* const* d_in, const int* in_sizes, int n_in,
                              void* d_out, int out_size) {
    const float* z  = (const float*)d_in[0];   // z_e      [32,4096,256] f32
    const float* cb = (const float*)d_in[1];   // codebook [1024,256]    f32
    float* out = (float*)d_out;

    const long long bnd = (long long)NROWS * D_;   // 33,554,432
    float *p_st = nullptr, *p_q = nullptr, *p_idx = nullptr;
    const long long os = (long long)out_size;

    if (os >= 2 * bnd + NROWS) {                 // [z_q_st | z_q | indices]
        p_st = out; p_q = out + bnd; p_idx = out + 2 * bnd;
    } else if (os == 2 * bnd) {                  // [z_q_st | z_q]
        p_st = out; p_q = out + bnd;
    } else if (os == bnd + NROWS) {              // [z_q_st | indices]
        p_st = out; p_idx = out + bnd;
    } else if (os == bnd) {                      // [z_q_st]
        p_st = out;
    } else if (os == NROWS) {                    // [indices]
        p_idx = out;
    } else {                                     // fallback
        p_st = out;
    }

    // Opt-in to >48KB dynamic smem (idempotent; no allocation involved)
    cudaFuncSetAttribute(vq_argmin_mma, cudaFuncAttributeMaxDynamicSharedMemorySize,
                         SM_TOTAL);

    esq_kernel<<<K_ / 8, 256>>>(cb);
    vq_argmin_mma<<<NROWS / 128, 256, SM_TOTAL>>>(z, cb, p_idx);
    fixup_kernel<<<512, 256>>>(z, cb, p_idx);
    if (p_st || p_q)
        gather_kernel<<<NROWS / 4, 256>>>(cb, z, p_st, p_q);
}